// round 6
// baseline (speedup 1.0000x reference)
#include <cuda_runtime.h>

// I5Pool: out[b,c,h,w] = max_{j<=w} x[b,c,h,j] * guide[b,0,h,j]
// x [8,256,128,128] fp32, guide [8,1,128,128] fp32.
// 4 CONSECUTIVE-h rows per warp -> 2KB contiguous load / 2KB contiguous store
// per warp, 16KB contiguous per block: DRAM page-hit friendly (memcpy-like).
// guide rows fetched per-h from L2 (kept resident via __ldcs/__stcs streaming
// on x/out). Warp shuffle max-scan, 4 interleaved rows.

#define B_ 8
#define C_ 256
#define H_ 128
#define W_ 128
#define ROWS (B_ * C_ * H_)     // 262144
#define WARPS_TOTAL (ROWS / 4)  // 65536

__global__ void __launch_bounds__(256) I5Pool_kernel(
    const float* __restrict__ x,
    const float* __restrict__ guide,
    float* __restrict__ out)
{
    const int wg   = (blockIdx.x * blockDim.x + threadIdx.x) >> 5;
    const int lane = threadIdx.x & 31;
    if (wg >= WARPS_TOTAL) return;

    // rows R..R+3, R = 4*wg, consecutive h within one (b,c) (4 | 128)
    const int R  = wg << 2;
    const int h0 = R & (H_ - 1);
    const int bc = R >> 7;           // b*C + c
    const int b  = bc >> 8;          // / C_

    const size_t xbase = (size_t)R * W_;                 // contiguous rows
    const size_t gbase = ((size_t)b * H_ + h0) * W_;     // contiguous guide rows

    // Front-batch: 4 guide rows (cached path, L2-resident) + 4 x rows (streaming)
    float4 gv[4], xv[4];
    #pragma unroll
    for (int r = 0; r < 4; r++)
        gv[r] = reinterpret_cast<const float4*>(guide + gbase + r * W_)[lane];
    #pragma unroll
    for (int r = 0; r < 4; r++)
        xv[r] = __ldcs(reinterpret_cast<const float4*>(x + xbase + r * W_) + lane);

    // local serial prefix-max per row
    float v0[4], v1[4], v2[4], v3[4];
    #pragma unroll
    for (int r = 0; r < 4; r++) {
        v0[r] = xv[r].x * gv[r].x;
        v1[r] = fmaxf(v0[r], xv[r].y * gv[r].y);
        v2[r] = fmaxf(v1[r], xv[r].z * gv[r].z);
        v3[r] = fmaxf(v2[r], xv[r].w * gv[r].w);
    }

    // 4 interleaved warp inclusive max-scans
    float m[4];
    #pragma unroll
    for (int r = 0; r < 4; r++) m[r] = v3[r];
    #pragma unroll
    for (int d = 1; d < 32; d <<= 1) {
        float o[4];
        #pragma unroll
        for (int r = 0; r < 4; r++) o[r] = __shfl_up_sync(0xffffffffu, m[r], d);
        if (lane >= d) {
            #pragma unroll
            for (int r = 0; r < 4; r++) m[r] = fmaxf(m[r], o[r]);
        }
    }

    // exclusive prefix, fold, store (2KB contiguous burst per warp)
    const float ninf = __int_as_float(0xff800000);
    #pragma unroll
    for (int r = 0; r < 4; r++) {
        float p = __shfl_up_sync(0xffffffffu, m[r], 1);
        if (lane == 0) p = ninf;
        float4 o;
        o.x = fmaxf(v0[r], p);
        o.y = fmaxf(v1[r], p);
        o.z = fmaxf(v2[r], p);
        o.w = fmaxf(v3[r], p);
        __stcs(reinterpret_cast<float4*>(out + xbase + r * W_) + lane, o);
    }
}

extern "C" void kernel_launch(void* const* d_in, const int* in_sizes, int n_in,
                              void* d_out, int out_size)
{
    const float* x     = (const float*)d_in[0];
    const float* guide = (const float*)d_in[1];
    float* out         = (float*)d_out;

    const int threads = 256;                          // 8 warps/block
    const int blocks  = (WARPS_TOTAL * 32) / threads; // 8192 blocks
    I5Pool_kernel<<<blocks, threads>>>(x, guide, out);
}